// round 16
// baseline (speedup 1.0000x reference)
#include <cuda_runtime.h>
#include <cuda_bf16.h>
#include <cuda_fp16.h>
#include <cstdint>

// Problem constants
#define NN   20000
#define EE   320000
#define FIN  128
#define HID  64
#define HC   256   // H*C
#define LL   4
#define NCOMB 1088 // q(256)|k(256)|v(256)|p(256)|skip(64)

#define SMEM_TRIPLE_BYTES ((2*128*36 + 2*32*72) * 4)

// ---------------- scratch (device globals; no allocation allowed) ----------------
__device__ __align__(16) float  g_h    [NN*HID];
__device__ __align__(16) float  g_A1   [NN*HID];
__device__ __align__(16) float  g_skip [NN*HID];
__device__ __align__(16) __half g_qkvh [NN*1024];   // q(256)|k(256)|v(256)|p(256) fp16
__device__ __align__(16) __half g_Rh   [NN*HC];     // R in fp16 (feeds half-A GEMM)
__device__ __align__(16) __half g_eash [EE*HID];    // edge features fp16, CSR order
__device__ __align__(16) float2 g_stats[NN];        // (mu, rstd) per row of h
__device__ __align__(16) float  g_Wc   [LL*HID*NCOMB];
__device__ __align__(16) float  g_bc   [LL*NCOMB];
__device__ __align__(16) float  g_M    [LL*HC*HID];
__device__ int g_deg [NN];
__device__ int g_off [NN+1];
__device__ int g_cur [NN];
__device__ int g_csrc[EE];
__device__ int g_ceid[EE];

// ---------------- small utility kernels ----------------
__global__ void zero_int_kernel(int* p, int n) {
    int i = blockIdx.x * blockDim.x + threadIdx.x;
    if (i < n) p[i] = 0;
}

__global__ void hist_kernel(const int* __restrict__ ei, int* __restrict__ deg, int E) {
    int e = blockIdx.x * blockDim.x + threadIdx.x;
    if (e < E) atomicAdd(&deg[ei[E + e]], 1);
}

// single-block exclusive scan of deg -> off, cur
__global__ void scan_kernel(const int* __restrict__ deg, int* __restrict__ off,
                            int* __restrict__ cur, int n, int total) {
    const int T = 1024;
    int tid = threadIdx.x;
    int chunk = (n + T - 1) / T;
    int s = tid * chunk;
    int e = s + chunk; if (e > n) e = n;
    int local = 0;
    for (int i = s; i < e; i++) local += deg[i];
    int lane = tid & 31, w = tid >> 5;
    int v = local;
    #pragma unroll
    for (int o = 1; o < 32; o <<= 1) {
        int t2 = __shfl_up_sync(0xffffffffu, v, o);
        if (lane >= o) v += t2;
    }
    __shared__ int wsum[32];
    if (lane == 31) wsum[w] = v;
    __syncthreads();
    if (w == 0) {
        int x = wsum[lane];
        #pragma unroll
        for (int o = 1; o < 32; o <<= 1) {
            int t2 = __shfl_up_sync(0xffffffffu, x, o);
            if (lane >= o) x += t2;
        }
        wsum[lane] = x;
    }
    __syncthreads();
    int incl = v + (w > 0 ? wsum[w - 1] : 0);
    int p = incl - local;
    for (int i = s; i < e; i++) { off[i] = p; cur[i] = p; p += deg[i]; }
    if (tid == 0) off[n] = total;
}

__global__ void scatter_kernel(const int* __restrict__ ei, int* __restrict__ cur,
                               int* __restrict__ csrc, int* __restrict__ ceid, int E) {
    int e = blockIdx.x * blockDim.x + threadIdx.x;
    if (e >= E) return;
    int s = ei[e];
    int d = ei[E + e];
    int pos = atomicAdd(&cur[d], 1);
    csrc[pos] = s;
    ceid[pos] = e;
}

// ---------------- weight prep: combined [64 x 1088] + bias ----------------
__global__ void prep_comb_kernel(const float* __restrict__ Wq, const float* __restrict__ bq,
                                 const float* __restrict__ Wk, const float* __restrict__ bk,
                                 const float* __restrict__ Wv, const float* __restrict__ bv,
                                 const float* __restrict__ We,
                                 const float* __restrict__ Wskip, const float* __restrict__ bskip,
                                 float* __restrict__ Wc, float* __restrict__ bc) {
    int idx = blockIdx.x * blockDim.x + threadIdx.x;
    if (idx >= LL * 65 * NCOMB) return;
    int col = idx % NCOMB;
    int t = idx / NCOMB;
    int f = t % 65;       // 64 == bias row
    int l = t / 65;
    float val;
    if (col < 256) {
        val = (f < 64) ? Wq[l * HID * HC + f * HC + col] : bq[l * HC + col];
    } else if (col < 512) {
        int c = col - 256;
        val = (f < 64) ? Wk[l * HID * HC + f * HC + c] : bk[l * HC + c];
    } else if (col < 768) {
        int c = col - 512;
        val = (f < 64) ? Wv[l * HID * HC + f * HC + c] : bv[l * HC + c];
    } else if (col < 1024) {
        int hj = col - 768;
        int h = hj >> 6, j = hj & 63;
        const float* arow = (f < 64) ? (Wq + l * HID * HC + f * HC) : (bq + l * HC);
        const float* wrow = We + l * HID * HC + j * HC;
        float s = 0.f;
        #pragma unroll 8
        for (int c = 0; c < 64; c++) s += arow[h * 64 + c] * wrow[h * 64 + c];
        val = s;
    } else {
        int c = col - 1024;
        val = (f < 64) ? Wskip[l * HID * HID + f * HID + c] : bskip[l * HID + c];
    }
    if (f < 64) Wc[l * HID * NCOMB + f * NCOMB + col] = val;
    else        bc[l * NCOMB + col] = val;
}

// M[l][h*64+j][d] = We[l][j][h*64+d] * 0.25
__global__ void prep_m_kernel(const float* __restrict__ We, float* __restrict__ M) {
    int idx = blockIdx.x * blockDim.x + threadIdx.x;
    if (idx >= LL * HC * HID) return;
    int d = idx & 63;
    int t = idx >> 6;
    int hj = t & 255;
    int l = t >> 8;
    int h = hj >> 6, j = hj & 63;
    M[idx] = We[l * HID * HC + j * HC + h * 64 + d] * 0.25f;
}

// ---------------- MMA helpers ----------------
__device__ __forceinline__ float tf32r(float x) {
    uint32_t u;
    asm("cvt.rna.tf32.f32 %0, %1;" : "=r"(u) : "f"(x));
    return __uint_as_float(u);
}
__device__ __forceinline__ void mma_tf32(float* d, const uint32_t* a, const uint32_t* b) {
    asm volatile("mma.sync.aligned.m16n8k8.row.col.f32.tf32.tf32.f32 "
        "{%0,%1,%2,%3}, {%4,%5,%6,%7}, {%8,%9}, {%0,%1,%2,%3};"
        : "+f"(d[0]), "+f"(d[1]), "+f"(d[2]), "+f"(d[3])
        : "r"(a[0]), "r"(a[1]), "r"(a[2]), "r"(a[3]), "r"(b[0]), "r"(b[1]));
}
__device__ __forceinline__ void mma_f16(float* d, const uint32_t* a, const uint32_t* b) {
    asm volatile("mma.sync.aligned.m16n8k16.row.col.f32.f16.f16.f32 "
        "{%0,%1,%2,%3}, {%4,%5,%6,%7}, {%8,%9}, {%0,%1,%2,%3};"
        : "+f"(d[0]), "+f"(d[1]), "+f"(d[2]), "+f"(d[3])
        : "r"(a[0]), "r"(a[1]), "r"(a[2]), "r"(a[3]), "r"(b[0]), "r"(b[1]));
}

// ---------------- fp16 tensor-core GEMM (m16n8k16, fp32 accum) ----------------
// LNF:    fuse LayerNorm+ReLU into A-load via stats_in + gamma/beta (K=64, fp32 A).
// STATS:  (fp32-out, Nc=64, gridDim.x==1) per-row (mu,rstd) of output -> stats_out.
// AHALF:  A operand is already fp16 (Ah); direct uint2 loads, no convert.
// Output modes:
//  qkvh != null : c<1024 -> half qkvh[r*1024+c]; c>=1024 -> fp32 C[r*64+c-1024] (skip)
//  Ch   != null : all cols -> half Ch[r*Nc+c]
//  else         : fp32 C[r*Nc+c] with bias/add1..3 (adds stride 64)
template<bool LNF, bool STATS, bool AHALF>
__global__ __launch_bounds__(256) void gemm_f16_kernel(
    const float* __restrict__ A, const __half* __restrict__ Ah,
    const int* __restrict__ rowmap,
    const float* __restrict__ B, const float* __restrict__ bias,
    const float2* __restrict__ stats_in, const float* __restrict__ lng, const float* __restrict__ lnb,
    const float* __restrict__ add1, const float* __restrict__ add2, const float* __restrict__ add3,
    float* __restrict__ C, __half* __restrict__ Ch, __half* __restrict__ qkvh,
    float2* __restrict__ stats_out,
    int Mr, int K, int Nc)
{
    __shared__ __half As[128][40];
    __shared__ __half Bs[64][40];
    __shared__ float Sp[STATS ? 512 : 4];   // [row][wn][sum/ssq]

    int tid = threadIdx.x;
    int warp = tid >> 5, lane = tid & 31;
    int wm = warp >> 1;            // 0..3
    int wn = warp & 1;             // 0..1
    int grp = lane >> 2, tg = lane & 3;
    int row0 = blockIdx.y * 128;
    int col0 = blockIdx.x * 64;

    float acc[2][4][4];
    #pragma unroll
    for (int mi = 0; mi < 2; mi++)
        #pragma unroll
        for (int ni = 0; ni < 4; ni++)
            #pragma unroll
            for (int r = 0; r < 4; r++) acc[mi][ni][r] = 0.f;

    for (int k0 = 0; k0 < K; k0 += 32) {
        // A tile: 128x32 -> half (fp32 convert or direct half loads)
        #pragma unroll
        for (int j = 0; j < 4; j++) {
            int idx = tid + j * 256;
            int r = idx >> 3;
            int c = (idx & 7) << 2;
            int gr = row0 + r;
            if (AHALF) {
                uint2 u = make_uint2(0u, 0u);
                if (gr < Mr)
                    u = *reinterpret_cast<const uint2*>(Ah + (size_t)gr * K + k0 + c);
                *reinterpret_cast<uint2*>(&As[r][c]) = u;
            } else {
                float4 av = make_float4(0.f, 0.f, 0.f, 0.f);
                if (gr < Mr) {
                    int grr = rowmap ? __ldg(rowmap + gr) : gr;
                    av = *reinterpret_cast<const float4*>(A + (size_t)grr * K + k0 + c);
                    if (LNF) {
                        float2 st = __ldg(stats_in + grr);
                        int fc = k0 + c;
                        av.x = fmaxf((av.x - st.x) * st.y * __ldg(lng + fc + 0) + __ldg(lnb + fc + 0), 0.f);
                        av.y = fmaxf((av.y - st.x) * st.y * __ldg(lng + fc + 1) + __ldg(lnb + fc + 1), 0.f);
                        av.z = fmaxf((av.z - st.x) * st.y * __ldg(lng + fc + 2) + __ldg(lnb + fc + 2), 0.f);
                        av.w = fmaxf((av.w - st.x) * st.y * __ldg(lng + fc + 3) + __ldg(lnb + fc + 3), 0.f);
                    }
                }
                __half2 h0 = __floats2half2_rn(av.x, av.y);
                __half2 h1 = __floats2half2_rn(av.z, av.w);
                uint2 u;
                u.x = *reinterpret_cast<uint32_t*>(&h0);
                u.y = *reinterpret_cast<uint32_t*>(&h1);
                *reinterpret_cast<uint2*>(&As[r][c]) = u;
            }
        }
        // B tile: 32x64 fp32 -> half transposed into Bs[n][k]
        #pragma unroll
        for (int j = 0; j < 2; j++) {
            int idx = tid + j * 256;
            int r = idx >> 4;              // k within tile
            int c = (idx & 15) << 2;       // n within tile
            int gc = col0 + c;
            float4 bv = make_float4(0.f, 0.f, 0.f, 0.f);
            if (gc < Nc)
                bv = *reinterpret_cast<const float4*>(B + (size_t)(k0 + r) * Nc + gc);
            Bs[c + 0][r] = __float2half(bv.x);
            Bs[c + 1][r] = __float2half(bv.y);
            Bs[c + 2][r] = __float2half(bv.z);
            Bs[c + 3][r] = __float2half(bv.w);
        }
        __syncthreads();
        #pragma unroll
        for (int kk = 0; kk < 32; kk += 16) {
            uint32_t a[2][4], b[4][2];
            int ar = wm * 32 + grp;
            #pragma unroll
            for (int mi = 0; mi < 2; mi++) {
                a[mi][0] = *reinterpret_cast<const uint32_t*>(&As[ar + mi * 16][kk + 2 * tg]);
                a[mi][1] = *reinterpret_cast<const uint32_t*>(&As[ar + mi * 16 + 8][kk + 2 * tg]);
                a[mi][2] = *reinterpret_cast<const uint32_t*>(&As[ar + mi * 16][kk + 8 + 2 * tg]);
                a[mi][3] = *reinterpret_cast<const uint32_t*>(&As[ar + mi * 16 + 8][kk + 8 + 2 * tg]);
            }
            #pragma unroll
            for (int ni = 0; ni < 4; ni++) {
                int bcn = wn * 32 + ni * 8 + grp;
                b[ni][0] = *reinterpret_cast<const uint32_t*>(&Bs[bcn][kk + 2 * tg]);
                b[ni][1] = *reinterpret_cast<const uint32_t*>(&Bs[bcn][kk + 8 + 2 * tg]);
            }
            #pragma unroll
            for (int mi = 0; mi < 2; mi++)
                #pragma unroll
                for (int ni = 0; ni < 4; ni++)
                    mma_f16(acc[mi][ni], a[mi], b[ni]);
        }
        __syncthreads();
    }

    // epilogue
    if (STATS) {
        #pragma unroll
        for (int mi = 0; mi < 2; mi++) {
            #pragma unroll
            for (int hf = 0; hf < 2; hf++) {
                int rl = wm * 32 + mi * 16 + grp + hf * 8;
                int r = row0 + rl;
                bool valid = (r < Mr);
                float sum = 0.f, ssq = 0.f;
                #pragma unroll
                for (int ni = 0; ni < 4; ni++) {
                    int c = wn * 32 + ni * 8 + tg * 2;
                    float v0 = acc[mi][ni][hf * 2];
                    float v1 = acc[mi][ni][hf * 2 + 1];
                    if (valid) {
                        if (bias) { v0 += bias[c]; v1 += bias[c + 1]; }
                        if (add1) { v0 += add1[(size_t)r * 64 + c]; v1 += add1[(size_t)r * 64 + c + 1]; }
                        if (add2) { v0 += add2[(size_t)r * 64 + c]; v1 += add2[(size_t)r * 64 + c + 1]; }
                        if (add3) { v0 += add3[(size_t)r * 64 + c]; v1 += add3[(size_t)r * 64 + c + 1]; }
                        C[(size_t)r * 64 + c]     = v0;
                        C[(size_t)r * 64 + c + 1] = v1;
                        sum += v0 + v1;
                        ssq += v0 * v0 + v1 * v1;
                    }
                }
                sum += __shfl_xor_sync(0xffffffffu, sum, 1);
                sum += __shfl_xor_sync(0xffffffffu, sum, 2);
                ssq += __shfl_xor_sync(0xffffffffu, ssq, 1);
                ssq += __shfl_xor_sync(0xffffffffu, ssq, 2);
                if (tg == 0) {
                    Sp[rl * 4 + wn * 2]     = sum;
                    Sp[rl * 4 + wn * 2 + 1] = ssq;
                }
            }
        }
        __syncthreads();
        if (tid < 128) {
            int r = row0 + tid;
            if (r < Mr) {
                float sum = Sp[tid * 4] + Sp[tid * 4 + 2];
                float ssq = Sp[tid * 4 + 1] + Sp[tid * 4 + 3];
                float mu = sum * (1.f / 64.f);
                float var = ssq * (1.f / 64.f) - mu * mu;
                stats_out[r] = make_float2(mu, rsqrtf(var + 1e-5f));
            }
        }
    } else {
        #pragma unroll
        for (int mi = 0; mi < 2; mi++) {
            int r0 = row0 + wm * 32 + mi * 16 + grp;
            #pragma unroll
            for (int ni = 0; ni < 4; ni++) {
                int c = col0 + wn * 32 + ni * 8 + tg * 2;
                if (c >= Nc) continue;
                #pragma unroll
                for (int half = 0; half < 2; half++) {
                    int r = r0 + half * 8;
                    if (r >= Mr) continue;
                    float v0 = acc[mi][ni][half * 2];
                    float v1 = acc[mi][ni][half * 2 + 1];
                    if (bias) { v0 += bias[c]; v1 += bias[c + 1]; }
                    if (qkvh) {
                        if (c < 1024) {
                            *reinterpret_cast<__half2*>(qkvh + (size_t)r * 1024 + c) =
                                __floats2half2_rn(v0, v1);
                        } else {
                            C[(size_t)r * 64 + c - 1024] = v0;
                            C[(size_t)r * 64 + c - 1023] = v1;
                        }
                    } else if (Ch) {
                        *reinterpret_cast<__half2*>(Ch + (size_t)r * Nc + c) =
                            __floats2half2_rn(v0, v1);
                    } else {
                        if (add1) { v0 += add1[(size_t)r * 64 + c]; v1 += add1[(size_t)r * 64 + c + 1]; }
                        if (add2) { v0 += add2[(size_t)r * 64 + c]; v1 += add2[(size_t)r * 64 + c + 1]; }
                        if (add3) { v0 += add3[(size_t)r * 64 + c]; v1 += add3[(size_t)r * 64 + c + 1]; }
                        C[(size_t)r * Nc + c]     = v0;
                        C[(size_t)r * Nc + c + 1] = v1;
                    }
                }
            }
        }
    }
}

// ---------------- 3xTF32 GEMM (node encoder + head; LNF fuses LN+ReLU on A) ----------------
template<bool LNF>
__global__ __launch_bounds__(256) void gemm_tf32x3_kernel(
    const float* __restrict__ A, const float* __restrict__ B, const float* __restrict__ bias,
    const float2* __restrict__ stats_in, const float* __restrict__ lng, const float* __restrict__ lnb,
    float* __restrict__ C, int Mr, int K, int Nc)
{
    extern __shared__ float sm[];
    float (*As)[36]  = reinterpret_cast<float(*)[36]>(sm);
    float (*AsL)[36] = reinterpret_cast<float(*)[36]>(sm + 128 * 36);
    float (*Bs)[72]  = reinterpret_cast<float(*)[72]>(sm + 2 * 128 * 36);
    float (*BsL)[72] = reinterpret_cast<float(*)[72]>(sm + 2 * 128 * 36 + 32 * 72);

    int tid = threadIdx.x;
    int warp = tid >> 5, lane = tid & 31;
    int wm = warp >> 1;
    int wn = warp & 1;
    int grp = lane >> 2, tg = lane & 3;
    int row0 = blockIdx.y * 128;
    int col0 = blockIdx.x * 64;

    float acc[2][4][4];
    #pragma unroll
    for (int mi = 0; mi < 2; mi++)
        #pragma unroll
        for (int ni = 0; ni < 4; ni++)
            #pragma unroll
            for (int r = 0; r < 4; r++) acc[mi][ni][r] = 0.f;

    for (int k0 = 0; k0 < K; k0 += 32) {
        #pragma unroll
        for (int j = 0; j < 4; j++) {
            int idx = tid + j * 256;
            int r = idx >> 3;
            int c = (idx & 7) << 2;
            int gr = row0 + r;
            float4 av = make_float4(0.f, 0.f, 0.f, 0.f);
            if (gr < Mr) {
                av = *reinterpret_cast<const float4*>(A + (size_t)gr * K + k0 + c);
                if (LNF) {
                    float2 st = __ldg(stats_in + gr);
                    int fc = k0 + c;
                    av.x = fmaxf((av.x - st.x) * st.y * __ldg(lng + fc + 0) + __ldg(lnb + fc + 0), 0.f);
                    av.y = fmaxf((av.y - st.x) * st.y * __ldg(lng + fc + 1) + __ldg(lnb + fc + 1), 0.f);
                    av.z = fmaxf((av.z - st.x) * st.y * __ldg(lng + fc + 2) + __ldg(lnb + fc + 2), 0.f);
                    av.w = fmaxf((av.w - st.x) * st.y * __ldg(lng + fc + 3) + __ldg(lnb + fc + 3), 0.f);
                }
            }
            float4 h4;
            h4.x = tf32r(av.x); h4.y = tf32r(av.y);
            h4.z = tf32r(av.z); h4.w = tf32r(av.w);
            *reinterpret_cast<float4*>(&As[r][c]) = h4;
            float4 l4;
            l4.x = tf32r(av.x - h4.x); l4.y = tf32r(av.y - h4.y);
            l4.z = tf32r(av.z - h4.z); l4.w = tf32r(av.w - h4.w);
            *reinterpret_cast<float4*>(&AsL[r][c]) = l4;
        }
        #pragma unroll
        for (int j = 0; j < 2; j++) {
            int idx = tid + j * 256;
            int r = idx >> 4;
            int c = (idx & 15) << 2;
            int gc = col0 + c;
            float4 bv = make_float4(0.f, 0.f, 0.f, 0.f);
            if (gc < Nc)
                bv = *reinterpret_cast<const float4*>(B + (size_t)(k0 + r) * Nc + gc);
            float4 h4;
            h4.x = tf32r(bv.x); h4.y = tf32r(bv.y);
            h4.z = tf32r(bv.z); h4.w = tf32r(bv.w);
            *reinterpret_cast<float4*>(&Bs[r][c]) = h4;
            float4 l4;
            l4.x = tf32r(bv.x - h4.x); l4.y = tf32r(bv.y - h4.y);
            l4.z = tf32r(bv.z - h4.z); l4.w = tf32r(bv.w - h4.w);
            *reinterpret_cast<float4*>(&BsL[r][c]) = l4;
        }
        __syncthreads();
        #pragma unroll
        for (int kk = 0; kk < 32; kk += 8) {
            uint32_t ah[2][4], bh[4][2], al[2][4], bl[4][2];
            int ar = wm * 32 + grp;
            #pragma unroll
            for (int mi = 0; mi < 2; mi++) {
                ah[mi][0] = __float_as_uint(As[ar + mi * 16][kk + tg]);
                ah[mi][1] = __float_as_uint(As[ar + mi * 16 + 8][kk + tg]);
                ah[mi][2] = __float_as_uint(As[ar + mi * 16][kk + tg + 4]);
                ah[mi][3] = __float_as_uint(As[ar + mi * 16 + 8][kk + tg + 4]);
                al[mi][0] = __float_as_uint(AsL[ar + mi * 16][kk + tg]);
                al[mi][1] = __float_as_uint(AsL[ar + mi * 16 + 8][kk + tg]);
                al[mi][2] = __float_as_uint(AsL[ar + mi * 16][kk + tg + 4]);
                al[mi][3] = __float_as_uint(AsL[ar + mi * 16 + 8][kk + tg + 4]);
            }
            #pragma unroll
            for (int ni = 0; ni < 4; ni++) {
                int bcn = wn * 32 + ni * 8 + grp;
                bh[ni][0] = __float_as_uint(Bs[kk + tg][bcn]);
                bh[ni][1] = __float_as_uint(Bs[kk + tg + 4][bcn]);
                bl[ni][0] = __float_as_uint(BsL[kk + tg][bcn]);
                bl[ni][1] = __float_as_uint(BsL[kk + tg + 4][bcn]);
            }
            #pragma unroll
            for (int mi = 0; mi < 2; mi++)
                #pragma unroll
                for (int ni = 0; ni < 4; ni++) {
                    mma_tf32(acc[mi][ni], ah[mi], bl[ni]);
                    mma_tf32(acc[mi][ni], al[mi], bh[ni]);
                    mma_tf32(acc[mi][ni], ah[mi], bh[ni]);
                }
        }
        __syncthreads();
    }

    #pragma unroll
    for (int mi = 0; mi < 2; mi++) {
        int r0 = row0 + wm * 32 + mi * 16 + grp;
        #pragma unroll
        for (int ni = 0; ni < 4; ni++) {
            int c = col0 + wn * 32 + ni * 8 + tg * 2;
            if (c >= Nc) continue;
            #pragma unroll
            for (int half = 0; half < 2; half++) {
                int r = r0 + half * 8;
                if (r >= Mr) continue;
                float v0 = acc[mi][ni][half * 2] + (bias ? bias[c] : 0.f);
                float v1 = acc[mi][ni][half * 2 + 1] + (bias ? bias[c + 1] : 0.f);
                C[(size_t)r * Nc + c]     = v0;
                C[(size_t)r * Nc + c + 1] = v1;
            }
        }
    }
}

// ---------------- fused per-node edge aggregation (softmax, all-fp16 gathers) ----------------
__device__ __forceinline__ void edge_accum(
    uint4 kr, uint4 vr, uint4 er, const float* qr, const float* pr,
    float* acc, float* rac, float& den)
{
    const __half2* kh = reinterpret_cast<const __half2*>(&kr);
    const __half2* vh = reinterpret_cast<const __half2*>(&vr);
    const __half2* eh = reinterpret_cast<const __half2*>(&er);
    float2 k0 = __half22float2(kh[0]), k1 = __half22float2(kh[1]);
    float2 k2 = __half22float2(kh[2]), k3 = __half22float2(kh[3]);
    float2 e0 = __half22float2(eh[0]), e1 = __half22float2(eh[1]);
    float2 e2 = __half22float2(eh[2]), e3 = __half22float2(eh[3]);
    float2 v0 = __half22float2(vh[0]), v1 = __half22float2(vh[1]);
    float2 v2 = __half22float2(vh[2]), v3 = __half22float2(vh[3]);

    float s = qr[0]*k0.x + qr[1]*k0.y + qr[2]*k1.x + qr[3]*k1.y
            + qr[4]*k2.x + qr[5]*k2.y + qr[6]*k3.x + qr[7]*k3.y
            + pr[0]*e0.x + pr[1]*e0.y + pr[2]*e1.x + pr[3]*e1.y
            + pr[4]*e2.x + pr[5]*e2.y + pr[6]*e3.x + pr[7]*e3.y;
    s += __shfl_xor_sync(0xffffffffu, s, 1, 8);
    s += __shfl_xor_sync(0xffffffffu, s, 2, 8);
    s += __shfl_xor_sync(0xffffffffu, s, 4, 8);
    float w = __expf(s * 0.125f);

    den += w;
    acc[0] += w*v0.x;  acc[1] += w*v0.y;
    acc[2] += w*v1.x;  acc[3] += w*v1.y;
    acc[4] += w*v2.x;  acc[5] += w*v2.y;
    acc[6] += w*v3.x;  acc[7] += w*v3.y;
    rac[0] += w*e0.x;  rac[1] += w*e0.y;
    rac[2] += w*e1.x;  rac[3] += w*e1.y;
    rac[4] += w*e2.x;  rac[5] += w*e2.y;
    rac[6] += w*e3.x;  rac[7] += w*e3.y;
}

// 2 warps per node: warp pair (2w, 2w+1) splits the node's CSR segment in half;
// partial sums (exact: no running max) are combined through smem by the even warp.
// 8 warps/block -> 4 nodes/block. NN % 4 == 0 -> exactly NN/4 blocks, no early exits.
// qkvh: half [node][1024] q@0 k@256 v@512 p@768. eash: half [epos][64].
__global__ __launch_bounds__(256) void edge_agg_kernel(
    const int* __restrict__ off, const int* __restrict__ csrc,
    const __half* __restrict__ eash, const __half* __restrict__ qkvh,
    float* __restrict__ A1, __half* __restrict__ Rh)
{
    __shared__ float Sden[4][32];
    __shared__ float Sacc[4][8][32];
    __shared__ float Srac[4][8][32];

    int warp = threadIdx.x >> 5;
    int lane = threadIdx.x & 31;
    int nodeLocal = warp >> 1;          // 0..3
    int halfid = warp & 1;              // 0 or 1
    int gw = blockIdx.x * 4 + nodeLocal;
    int ch0 = lane << 3;
    int ealn = (lane & 7) << 3;

    float qr[8], pr[8];
    {
        const __half* qpp = qkvh + (size_t)gw * 1024 + ch0;
        uint4 qu = *reinterpret_cast<const uint4*>(qpp);
        uint4 pu = *reinterpret_cast<const uint4*>(qpp + 768);
        const __half2* qh = reinterpret_cast<const __half2*>(&qu);
        const __half2* ph = reinterpret_cast<const __half2*>(&pu);
        #pragma unroll
        for (int i = 0; i < 4; i++) {
            float2 qf = __half22float2(qh[i]);
            float2 pf = __half22float2(ph[i]);
            qr[2*i] = qf.x; qr[2*i+1] = qf.y;
            pr[2*i] = pf.x; pr[2*i+1] = pf.y;
        }
    }
    float den = 0.f;
    float acc[8], rac[8];
    #pragma unroll
    for (int r = 0; r < 8; r++) { acc[r] = 0.f; rac[r] = 0.f; }

    int beg = off[gw], end = off[gw + 1];
    int cnt = end - beg;
    int c0 = (cnt + 1) >> 1;              // first-half size
    int mybeg = beg + halfid * c0;
    int myend = halfid ? end : beg + c0;

    int epos = mybeg;
    int n2 = mybeg + ((myend - mybeg) & ~1);
    for (; epos < n2; epos += 2) {
        int s0 = __ldg(csrc + epos);
        int s1 = __ldg(csrc + epos + 1);
        const __half* kp0 = qkvh + (size_t)s0 * 1024 + 256 + ch0;
        const __half* kp1 = qkvh + (size_t)s1 * 1024 + 256 + ch0;
        uint4 kr0 = *reinterpret_cast<const uint4*>(kp0);
        uint4 vr0 = *reinterpret_cast<const uint4*>(kp0 + 256);
        uint4 er0 = *reinterpret_cast<const uint4*>(eash + (size_t)epos * 64 + ealn);
        uint4 kr1 = *reinterpret_cast<const uint4*>(kp1);
        uint4 vr1 = *reinterpret_cast<const uint4*>(kp1 + 256);
        uint4 er1 = *reinterpret_cast<const uint4*>(eash + (size_t)(epos + 1) * 64 + ealn);
        edge_accum(kr0, vr0, er0, qr, pr, acc, rac, den);
        edge_accum(kr1, vr1, er1, qr, pr, acc, rac, den);
    }
    if (epos < myend) {
        int s0 = __ldg(csrc + epos);
        const __half* kp0 = qkvh + (size_t)s0 * 1024 + 256 + ch0;
        uint4 kr0 = *reinterpret_cast<const uint4*>(kp0);
        uint4 vr0 = *reinterpret_cast<const uint4*>(kp0 + 256);
        uint4 er0 = *reinterpret_cast<const uint4*>(eash + (size_t)epos * 64 + ealn);
        edge_accum(kr0, vr0, er0, qr, pr, acc, rac, den);
    }

    // odd warp publishes partials
    if (halfid == 1) {
        Sden[nodeLocal][lane] = den;
        #pragma unroll
        for (int r = 0; r < 8; r++) {
            Sacc[nodeLocal][r][lane] = acc[r];
            Srac[nodeLocal][r][lane] = rac[r];
        }
    }
    __syncthreads();
    if (halfid == 1) return;

    // even warp combines + epilogue
    den += Sden[nodeLocal][lane];
    #pragma unroll
    for (int r = 0; r < 8; r++) {
        acc[r] += Sacc[nodeLocal][r][lane];
        rac[r] += Srac[nodeLocal][r][lane];
    }

    float dinv = 1.f / (den + 1e-16f);
    float a1[8];
    #pragma unroll
    for (int r = 0; r < 8; r++) a1[r] = acc[r] * dinv * 0.25f;
    #pragma unroll
    for (int r = 0; r < 8; r++) {
        a1[r] += __shfl_xor_sync(0xffffffffu, a1[r], 8);
        a1[r] += __shfl_xor_sync(0xffffffffu, a1[r], 16);
    }
    if (lane < 8) {
        *reinterpret_cast<float4*>(A1 + (size_t)gw * 64 + ealn) =
            make_float4(a1[0], a1[1], a1[2], a1[3]);
        *reinterpret_cast<float4*>(A1 + (size_t)gw * 64 + ealn + 4) =
            make_float4(a1[4], a1[5], a1[6], a1[7]);
    }
    uint4 ru;
    __half2 r0 = __floats2half2_rn(rac[0] * dinv, rac[1] * dinv);
    __half2 r1 = __floats2half2_rn(rac[2] * dinv, rac[3] * dinv);
    __half2 r2 = __floats2half2_rn(rac[4] * dinv, rac[5] * dinv);
    __half2 r3 = __floats2half2_rn(rac[6] * dinv, rac[7] * dinv);
    ru.x = *reinterpret_cast<uint32_t*>(&r0);
    ru.y = *reinterpret_cast<uint32_t*>(&r1);
    ru.z = *reinterpret_cast<uint32_t*>(&r2);
    ru.w = *reinterpret_cast<uint32_t*>(&r3);
    *reinterpret_cast<uint4*>(Rh + (size_t)gw * 256 + ch0) = ru;
}

// ---------------- host launch ----------------
extern "C" void kernel_launch(void* const* d_in, const int* in_sizes, int n_in,
                              void* d_out, int out_size) {
    const float* x         = (const float*)d_in[0];
    const int*   ei        = (const int*)  d_in[1];
    const float* edge_attr = (const float*)d_in[2];
    const float* node_W    = (const float*)d_in[3];
    const float* node_b    = (const float*)d_in[4];
    const float* eenc_W    = (const float*)d_in[5];
    const float* eenc_b    = (const float*)d_in[6];
    const float* Wq        = (const float*)d_in[7];
    const float* bq        = (const float*)d_in[8];
    const float* Wk        = (const float*)d_in[9];
    const float* bk        = (const float*)d_in[10];
    const float* Wv        = (const float*)d_in[11];
    const float* bv        = (const float*)d_in[12];
    const float* We        = (const float*)d_in[13];
    const float* Wskip     = (const float*)d_in[14];
    const float* bskip     = (const float*)d_in[15];
    const float* ln_g      = (const float*)d_in[16];
    const float* ln_b      = (const float*)d_in[17];
    const float* lin_W     = (const float*)d_in[18];
    const float* lin_b     = (const float*)d_in[19];
    float* out = (float*)d_out;

    cudaFuncSetAttribute(gemm_tf32x3_kernel<false>,
                         cudaFuncAttributeMaxDynamicSharedMemorySize, SMEM_TRIPLE_BYTES);
    cudaFuncSetAttribute(gemm_tf32x3_kernel<true>,
                         cudaFuncAttributeMaxDynamicSharedMemorySize, SMEM_TRIPLE_BYTES);

    float *h_, *A1_, *skip_, *Wc_, *bc_, *M_;
    float2* stats_;
    __half *qkvh_, *eash_, *Rh_;
    int *deg_, *off_, *cur_, *csrc_, *ceid_;
    cudaGetSymbolAddress((void**)&h_,    g_h);
    cudaGetSymbolAddress((void**)&A1_,   g_A1);
    cudaGetSymbolAddress((void**)&skip_, g_skip);
    cudaGetSymbolAddress((void**)&qkvh_, g_qkvh);
    cudaGetSymbolAddress((void**)&Rh_,   g_Rh);
    cudaGetSymbolAddress((void**)&eash_, g_eash);
    cudaGetSymbolAddress((void**)&stats_,g_stats);
    cudaGetSymbolAddress((void**)&Wc_,   g_Wc);
    cudaGetSymbolAddress((void**)&bc_,   g_bc);
    cudaGetSymbolAddress((void**)&M_,    g_M);
    cudaGetSymbolAddress((void**)&deg_,  g_deg);
    cudaGetSymbolAddress((void**)&off_,  g_off);
    cudaGetSymbolAddress((void**)&cur_,  g_cur);
    cudaGetSymbolAddress((void**)&csrc_, g_csrc);
    cudaGetSymbolAddress((void**)&ceid_, g_ceid);

    // CSR build
    zero_int_kernel<<<(NN + 255) / 256, 256>>>(deg_, NN);
    hist_kernel<<<(EE + 255) / 256, 256>>>(ei, deg_, EE);
    scan_kernel<<<1, 1024>>>(deg_, off_, cur_, NN, EE);
    scatter_kernel<<<(EE + 255) / 256, 256>>>(ei, cur_, csrc_, ceid_, EE);

    // folded/combined weights
    prep_comb_kernel<<<(LL * 65 * NCOMB + 255) / 256, 256>>>(
        Wq, bq, Wk, bk, Wv, bv, We, Wskip, bskip, Wc_, bc_);
    prep_m_kernel<<<(LL * HC * HID + 255) / 256, 256>>>(We, M_);

    // edge encoder: gather rows in CSR order (rowmap=ceid), fp16 out
    {
        dim3 grid(1, (EE + 127) / 128);
        gemm_f16_kernel<false, false, false><<<grid, 256>>>(
            edge_attr, nullptr, ceid_, eenc_W, eenc_b, nullptr, nullptr, nullptr,
            nullptr, nullptr, nullptr, nullptr, eash_, nullptr, nullptr, EE, 64, 64);
    }
    // node encoder: 3xTF32 hedge
    {
        dim3 grid(1, (NN + 127) / 128);
        gemm_tf32x3_kernel<false><<<grid, 256, SMEM_TRIPLE_BYTES>>>(
            x, node_W, node_b, nullptr, nullptr, nullptr, h_, NN, 128, 64);
    }

    const int rowsN = (NN + 127) / 128;
    for (int l = 0; l < LL; l++) {
        // fused [q|k|v|p|skip] GEMM; layers>0 fuse LN+ReLU via stats from prev R@M
        dim3 grid((NCOMB + 63) / 64, rowsN);
        if (l == 0) {
            gemm_f16_kernel<false, false, false><<<grid, 256>>>(
                h_, nullptr, nullptr, Wc_ + l * HID * NCOMB, bc_ + l * NCOMB,
                nullptr, nullptr, nullptr,
                nullptr, nullptr, nullptr, skip_, nullptr, qkvh_, nullptr, NN, 64, NCOMB);
        } else {
            gemm_f16_kernel<true, false, false><<<grid, 256>>>(
                h_, nullptr, nullptr, Wc_ + l * HID * NCOMB, bc_ + l * NCOMB,
                stats_, ln_g + l * 64, ln_b + l * 64,
                nullptr, nullptr, nullptr, skip_, nullptr, qkvh_, nullptr, NN, 64, NCOMB);
        }
        // 2 warps/node: NN/4 blocks of 256 threads
        edge_agg_kernel<<<NN / 4, 256>>>(off_, csrc_, eash_, qkvh_, A1_, Rh_);
        // h = Rh@M + A1 + skip (+ h residual for l>0); emit per-row LN stats; A in fp16
        dim3 grid2(1, rowsN);
        gemm_f16_kernel<false, true, true><<<grid2, 256>>>(
            nullptr, Rh_, nullptr, M_ + l * HC * HID, nullptr,
            nullptr, nullptr, nullptr,
            A1_, skip_, (l > 0 ? h_ : nullptr), h_, nullptr, nullptr, stats_, NN, 256, 64);
    }

    // head: LN(g[0],b[0])+ReLU fused into A-load, 3xTF32
    {
        dim3 grid(1, rowsN);
        gemm_tf32x3_kernel<true><<<grid, 256, SMEM_TRIPLE_BYTES>>>(
            h_, lin_W, lin_b, stats_, ln_g, ln_b, out, NN, 64, 32);
    }
}

// round 17
// speedup vs baseline: 1.0862x; 1.0862x over previous
#include <cuda_runtime.h>
#include <cuda_bf16.h>
#include <cuda_fp16.h>
#include <cstdint>

// Problem constants
#define NN   20000
#define EE   320000
#define FIN  128
#define HID  64
#define HC   256   // H*C
#define LL   4
#define NCOMB 1088 // q(256)|k(256)|v(256)|p(256)|skip(64)

#define SMEM_TRIPLE_BYTES ((2*128*36 + 2*32*72) * 4)

// ---------------- scratch (device globals; no allocation allowed) ----------------
__device__ __align__(16) float  g_h    [NN*HID];
__device__ __align__(16) float  g_A1   [NN*HID];
__device__ __align__(16) float  g_skip [NN*HID];
__device__ __align__(16) __half g_qkvh [NN*1024];   // q(256)|k(256)|v(256)|p(256) fp16
__device__ __align__(16) __half g_Rh   [NN*HC];     // R in fp16 (feeds half-A GEMM)
__device__ __align__(16) __half g_eash [EE*HID];    // edge features fp16, CSR order
__device__ __align__(16) float2 g_stats[NN];        // (mu, rstd) per row of h
__device__ __align__(16) float  g_Wc   [LL*HID*NCOMB];
__device__ __align__(16) float  g_bc   [LL*NCOMB];
__device__ __align__(16) float  g_M    [LL*HC*HID];
__device__ int g_deg [NN];
__device__ int g_off [NN+1];
__device__ int g_cur [NN];
__device__ int g_csrc[EE];
__device__ int g_ceid[EE];

// ---------------- small utility kernels ----------------
__global__ void zero_int_kernel(int* p, int n) {
    int i = blockIdx.x * blockDim.x + threadIdx.x;
    if (i < n) p[i] = 0;
}

__global__ void hist_kernel(const int* __restrict__ ei, int* __restrict__ deg, int E) {
    int e = blockIdx.x * blockDim.x + threadIdx.x;
    if (e < E) atomicAdd(&deg[ei[E + e]], 1);
}

// single-block exclusive scan of deg -> off, cur
__global__ void scan_kernel(const int* __restrict__ deg, int* __restrict__ off,
                            int* __restrict__ cur, int n, int total) {
    const int T = 1024;
    int tid = threadIdx.x;
    int chunk = (n + T - 1) / T;
    int s = tid * chunk;
    int e = s + chunk; if (e > n) e = n;
    int local = 0;
    for (int i = s; i < e; i++) local += deg[i];
    int lane = tid & 31, w = tid >> 5;
    int v = local;
    #pragma unroll
    for (int o = 1; o < 32; o <<= 1) {
        int t2 = __shfl_up_sync(0xffffffffu, v, o);
        if (lane >= o) v += t2;
    }
    __shared__ int wsum[32];
    if (lane == 31) wsum[w] = v;
    __syncthreads();
    if (w == 0) {
        int x = wsum[lane];
        #pragma unroll
        for (int o = 1; o < 32; o <<= 1) {
            int t2 = __shfl_up_sync(0xffffffffu, x, o);
            if (lane >= o) x += t2;
        }
        wsum[lane] = x;
    }
    __syncthreads();
    int incl = v + (w > 0 ? wsum[w - 1] : 0);
    int p = incl - local;
    for (int i = s; i < e; i++) { off[i] = p; cur[i] = p; p += deg[i]; }
    if (tid == 0) off[n] = total;
}

__global__ void scatter_kernel(const int* __restrict__ ei, int* __restrict__ cur,
                               int* __restrict__ csrc, int* __restrict__ ceid, int E) {
    int e = blockIdx.x * blockDim.x + threadIdx.x;
    if (e >= E) return;
    int s = ei[e];
    int d = ei[E + e];
    int pos = atomicAdd(&cur[d], 1);
    csrc[pos] = s;
    ceid[pos] = e;
}

// ---------------- weight prep: combined [64 x 1088] + bias ----------------
__global__ void prep_comb_kernel(const float* __restrict__ Wq, const float* __restrict__ bq,
                                 const float* __restrict__ Wk, const float* __restrict__ bk,
                                 const float* __restrict__ Wv, const float* __restrict__ bv,
                                 const float* __restrict__ We,
                                 const float* __restrict__ Wskip, const float* __restrict__ bskip,
                                 float* __restrict__ Wc, float* __restrict__ bc) {
    int idx = blockIdx.x * blockDim.x + threadIdx.x;
    if (idx >= LL * 65 * NCOMB) return;
    int col = idx % NCOMB;
    int t = idx / NCOMB;
    int f = t % 65;       // 64 == bias row
    int l = t / 65;
    float val;
    if (col < 256) {
        val = (f < 64) ? Wq[l * HID * HC + f * HC + col] : bq[l * HC + col];
    } else if (col < 512) {
        int c = col - 256;
        val = (f < 64) ? Wk[l * HID * HC + f * HC + c] : bk[l * HC + c];
    } else if (col < 768) {
        int c = col - 512;
        val = (f < 64) ? Wv[l * HID * HC + f * HC + c] : bv[l * HC + c];
    } else if (col < 1024) {
        int hj = col - 768;
        int h = hj >> 6, j = hj & 63;
        const float* arow = (f < 64) ? (Wq + l * HID * HC + f * HC) : (bq + l * HC);
        const float* wrow = We + l * HID * HC + j * HC;
        float s = 0.f;
        #pragma unroll 8
        for (int c = 0; c < 64; c++) s += arow[h * 64 + c] * wrow[h * 64 + c];
        val = s;
    } else {
        int c = col - 1024;
        val = (f < 64) ? Wskip[l * HID * HID + f * HID + c] : bskip[l * HID + c];
    }
    if (f < 64) Wc[l * HID * NCOMB + f * NCOMB + col] = val;
    else        bc[l * NCOMB + col] = val;
}

// M[l][h*64+j][d] = We[l][j][h*64+d] * 0.25
__global__ void prep_m_kernel(const float* __restrict__ We, float* __restrict__ M) {
    int idx = blockIdx.x * blockDim.x + threadIdx.x;
    if (idx >= LL * HC * HID) return;
    int d = idx & 63;
    int t = idx >> 6;
    int hj = t & 255;
    int l = t >> 8;
    int h = hj >> 6, j = hj & 63;
    M[idx] = We[l * HID * HC + j * HC + h * 64 + d] * 0.25f;
}

// ---------------- MMA helpers ----------------
__device__ __forceinline__ float tf32r(float x) {
    uint32_t u;
    asm("cvt.rna.tf32.f32 %0, %1;" : "=r"(u) : "f"(x));
    return __uint_as_float(u);
}
__device__ __forceinline__ void mma_tf32(float* d, const uint32_t* a, const uint32_t* b) {
    asm volatile("mma.sync.aligned.m16n8k8.row.col.f32.tf32.tf32.f32 "
        "{%0,%1,%2,%3}, {%4,%5,%6,%7}, {%8,%9}, {%0,%1,%2,%3};"
        : "+f"(d[0]), "+f"(d[1]), "+f"(d[2]), "+f"(d[3])
        : "r"(a[0]), "r"(a[1]), "r"(a[2]), "r"(a[3]), "r"(b[0]), "r"(b[1]));
}
__device__ __forceinline__ void mma_f16(float* d, const uint32_t* a, const uint32_t* b) {
    asm volatile("mma.sync.aligned.m16n8k16.row.col.f32.f16.f16.f32 "
        "{%0,%1,%2,%3}, {%4,%5,%6,%7}, {%8,%9}, {%0,%1,%2,%3};"
        : "+f"(d[0]), "+f"(d[1]), "+f"(d[2]), "+f"(d[3])
        : "r"(a[0]), "r"(a[1]), "r"(a[2]), "r"(a[3]), "r"(b[0]), "r"(b[1]));
}

// ---------------- fp16 tensor-core GEMM (m16n8k16, fp32 accum) ----------------
// LNF:    fuse LayerNorm+ReLU into A-load via stats_in + gamma/beta (K=64, fp32 A).
// STATS:  (fp32-out, Nc=64, gridDim.x==1) per-row (mu,rstd) of output -> stats_out.
// AHALF:  A operand is already fp16 (Ah); direct uint2 loads, no convert.
// Output modes:
//  qkvh != null : c<1024 -> half qkvh[r*1024+c]; c>=1024 -> fp32 C[r*64+c-1024] (skip)
//  Ch   != null : all cols -> half Ch[r*Nc+c]
//  else         : fp32 C[r*Nc+c] with bias/add1..3 (adds stride 64)
template<bool LNF, bool STATS, bool AHALF>
__global__ __launch_bounds__(256) void gemm_f16_kernel(
    const float* __restrict__ A, const __half* __restrict__ Ah,
    const int* __restrict__ rowmap,
    const float* __restrict__ B, const float* __restrict__ bias,
    const float2* __restrict__ stats_in, const float* __restrict__ lng, const float* __restrict__ lnb,
    const float* __restrict__ add1, const float* __restrict__ add2, const float* __restrict__ add3,
    float* __restrict__ C, __half* __restrict__ Ch, __half* __restrict__ qkvh,
    float2* __restrict__ stats_out,
    int Mr, int K, int Nc)
{
    __shared__ __half As[128][40];
    __shared__ __half Bs[64][40];
    __shared__ float Sp[STATS ? 512 : 4];   // [row][wn][sum/ssq]

    int tid = threadIdx.x;
    int warp = tid >> 5, lane = tid & 31;
    int wm = warp >> 1;            // 0..3
    int wn = warp & 1;             // 0..1
    int grp = lane >> 2, tg = lane & 3;
    int row0 = blockIdx.y * 128;
    int col0 = blockIdx.x * 64;

    float acc[2][4][4];
    #pragma unroll
    for (int mi = 0; mi < 2; mi++)
        #pragma unroll
        for (int ni = 0; ni < 4; ni++)
            #pragma unroll
            for (int r = 0; r < 4; r++) acc[mi][ni][r] = 0.f;

    for (int k0 = 0; k0 < K; k0 += 32) {
        // A tile: 128x32 -> half (fp32 convert or direct half loads)
        #pragma unroll
        for (int j = 0; j < 4; j++) {
            int idx = tid + j * 256;
            int r = idx >> 3;
            int c = (idx & 7) << 2;
            int gr = row0 + r;
            if (AHALF) {
                uint2 u = make_uint2(0u, 0u);
                if (gr < Mr)
                    u = *reinterpret_cast<const uint2*>(Ah + (size_t)gr * K + k0 + c);
                *reinterpret_cast<uint2*>(&As[r][c]) = u;
            } else {
                float4 av = make_float4(0.f, 0.f, 0.f, 0.f);
                if (gr < Mr) {
                    int grr = rowmap ? __ldg(rowmap + gr) : gr;
                    av = *reinterpret_cast<const float4*>(A + (size_t)grr * K + k0 + c);
                    if (LNF) {
                        float2 st = __ldg(stats_in + grr);
                        int fc = k0 + c;
                        av.x = fmaxf((av.x - st.x) * st.y * __ldg(lng + fc + 0) + __ldg(lnb + fc + 0), 0.f);
                        av.y = fmaxf((av.y - st.x) * st.y * __ldg(lng + fc + 1) + __ldg(lnb + fc + 1), 0.f);
                        av.z = fmaxf((av.z - st.x) * st.y * __ldg(lng + fc + 2) + __ldg(lnb + fc + 2), 0.f);
                        av.w = fmaxf((av.w - st.x) * st.y * __ldg(lng + fc + 3) + __ldg(lnb + fc + 3), 0.f);
                    }
                }
                __half2 h0 = __floats2half2_rn(av.x, av.y);
                __half2 h1 = __floats2half2_rn(av.z, av.w);
                uint2 u;
                u.x = *reinterpret_cast<uint32_t*>(&h0);
                u.y = *reinterpret_cast<uint32_t*>(&h1);
                *reinterpret_cast<uint2*>(&As[r][c]) = u;
            }
        }
        // B tile: 32x64 fp32 -> half transposed into Bs[n][k]
        #pragma unroll
        for (int j = 0; j < 2; j++) {
            int idx = tid + j * 256;
            int r = idx >> 4;              // k within tile
            int c = (idx & 15) << 2;       // n within tile
            int gc = col0 + c;
            float4 bv = make_float4(0.f, 0.f, 0.f, 0.f);
            if (gc < Nc)
                bv = *reinterpret_cast<const float4*>(B + (size_t)(k0 + r) * Nc + gc);
            Bs[c + 0][r] = __float2half(bv.x);
            Bs[c + 1][r] = __float2half(bv.y);
            Bs[c + 2][r] = __float2half(bv.z);
            Bs[c + 3][r] = __float2half(bv.w);
        }
        __syncthreads();
        #pragma unroll
        for (int kk = 0; kk < 32; kk += 16) {
            uint32_t a[2][4], b[4][2];
            int ar = wm * 32 + grp;
            #pragma unroll
            for (int mi = 0; mi < 2; mi++) {
                a[mi][0] = *reinterpret_cast<const uint32_t*>(&As[ar + mi * 16][kk + 2 * tg]);
                a[mi][1] = *reinterpret_cast<const uint32_t*>(&As[ar + mi * 16 + 8][kk + 2 * tg]);
                a[mi][2] = *reinterpret_cast<const uint32_t*>(&As[ar + mi * 16][kk + 8 + 2 * tg]);
                a[mi][3] = *reinterpret_cast<const uint32_t*>(&As[ar + mi * 16 + 8][kk + 8 + 2 * tg]);
            }
            #pragma unroll
            for (int ni = 0; ni < 4; ni++) {
                int bcn = wn * 32 + ni * 8 + grp;
                b[ni][0] = *reinterpret_cast<const uint32_t*>(&Bs[bcn][kk + 2 * tg]);
                b[ni][1] = *reinterpret_cast<const uint32_t*>(&Bs[bcn][kk + 8 + 2 * tg]);
            }
            #pragma unroll
            for (int mi = 0; mi < 2; mi++)
                #pragma unroll
                for (int ni = 0; ni < 4; ni++)
                    mma_f16(acc[mi][ni], a[mi], b[ni]);
        }
        __syncthreads();
    }

    // epilogue
    if (STATS) {
        #pragma unroll
        for (int mi = 0; mi < 2; mi++) {
            #pragma unroll
            for (int hf = 0; hf < 2; hf++) {
                int rl = wm * 32 + mi * 16 + grp + hf * 8;
                int r = row0 + rl;
                bool valid = (r < Mr);
                float sum = 0.f, ssq = 0.f;
                #pragma unroll
                for (int ni = 0; ni < 4; ni++) {
                    int c = wn * 32 + ni * 8 + tg * 2;
                    float v0 = acc[mi][ni][hf * 2];
                    float v1 = acc[mi][ni][hf * 2 + 1];
                    if (valid) {
                        if (bias) { v0 += bias[c]; v1 += bias[c + 1]; }
                        if (add1) { v0 += add1[(size_t)r * 64 + c]; v1 += add1[(size_t)r * 64 + c + 1]; }
                        if (add2) { v0 += add2[(size_t)r * 64 + c]; v1 += add2[(size_t)r * 64 + c + 1]; }
                        if (add3) { v0 += add3[(size_t)r * 64 + c]; v1 += add3[(size_t)r * 64 + c + 1]; }
                        C[(size_t)r * 64 + c]     = v0;
                        C[(size_t)r * 64 + c + 1] = v1;
                        sum += v0 + v1;
                        ssq += v0 * v0 + v1 * v1;
                    }
                }
                sum += __shfl_xor_sync(0xffffffffu, sum, 1);
                sum += __shfl_xor_sync(0xffffffffu, sum, 2);
                ssq += __shfl_xor_sync(0xffffffffu, ssq, 1);
                ssq += __shfl_xor_sync(0xffffffffu, ssq, 2);
                if (tg == 0) {
                    Sp[rl * 4 + wn * 2]     = sum;
                    Sp[rl * 4 + wn * 2 + 1] = ssq;
                }
            }
        }
        __syncthreads();
        if (tid < 128) {
            int r = row0 + tid;
            if (r < Mr) {
                float sum = Sp[tid * 4] + Sp[tid * 4 + 2];
                float ssq = Sp[tid * 4 + 1] + Sp[tid * 4 + 3];
                float mu = sum * (1.f / 64.f);
                float var = ssq * (1.f / 64.f) - mu * mu;
                stats_out[r] = make_float2(mu, rsqrtf(var + 1e-5f));
            }
        }
    } else {
        #pragma unroll
        for (int mi = 0; mi < 2; mi++) {
            int r0 = row0 + wm * 32 + mi * 16 + grp;
            #pragma unroll
            for (int ni = 0; ni < 4; ni++) {
                int c = col0 + wn * 32 + ni * 8 + tg * 2;
                if (c >= Nc) continue;
                #pragma unroll
                for (int half = 0; half < 2; half++) {
                    int r = r0 + half * 8;
                    if (r >= Mr) continue;
                    float v0 = acc[mi][ni][half * 2];
                    float v1 = acc[mi][ni][half * 2 + 1];
                    if (bias) { v0 += bias[c]; v1 += bias[c + 1]; }
                    if (qkvh) {
                        if (c < 1024) {
                            *reinterpret_cast<__half2*>(qkvh + (size_t)r * 1024 + c) =
                                __floats2half2_rn(v0, v1);
                        } else {
                            C[(size_t)r * 64 + c - 1024] = v0;
                            C[(size_t)r * 64 + c - 1023] = v1;
                        }
                    } else if (Ch) {
                        *reinterpret_cast<__half2*>(Ch + (size_t)r * Nc + c) =
                            __floats2half2_rn(v0, v1);
                    } else {
                        if (add1) { v0 += add1[(size_t)r * 64 + c]; v1 += add1[(size_t)r * 64 + c + 1]; }
                        if (add2) { v0 += add2[(size_t)r * 64 + c]; v1 += add2[(size_t)r * 64 + c + 1]; }
                        if (add3) { v0 += add3[(size_t)r * 64 + c]; v1 += add3[(size_t)r * 64 + c + 1]; }
                        C[(size_t)r * Nc + c]     = v0;
                        C[(size_t)r * Nc + c + 1] = v1;
                    }
                }
            }
        }
    }
}

// ---------------- 3xTF32 GEMM (node encoder + head; LNF fuses LN+ReLU on A) ----------------
template<bool LNF>
__global__ __launch_bounds__(256) void gemm_tf32x3_kernel(
    const float* __restrict__ A, const float* __restrict__ B, const float* __restrict__ bias,
    const float2* __restrict__ stats_in, const float* __restrict__ lng, const float* __restrict__ lnb,
    float* __restrict__ C, int Mr, int K, int Nc)
{
    extern __shared__ float sm[];
    float (*As)[36]  = reinterpret_cast<float(*)[36]>(sm);
    float (*AsL)[36] = reinterpret_cast<float(*)[36]>(sm + 128 * 36);
    float (*Bs)[72]  = reinterpret_cast<float(*)[72]>(sm + 2 * 128 * 36);
    float (*BsL)[72] = reinterpret_cast<float(*)[72]>(sm + 2 * 128 * 36 + 32 * 72);

    int tid = threadIdx.x;
    int warp = tid >> 5, lane = tid & 31;
    int wm = warp >> 1;
    int wn = warp & 1;
    int grp = lane >> 2, tg = lane & 3;
    int row0 = blockIdx.y * 128;
    int col0 = blockIdx.x * 64;

    float acc[2][4][4];
    #pragma unroll
    for (int mi = 0; mi < 2; mi++)
        #pragma unroll
        for (int ni = 0; ni < 4; ni++)
            #pragma unroll
            for (int r = 0; r < 4; r++) acc[mi][ni][r] = 0.f;

    for (int k0 = 0; k0 < K; k0 += 32) {
        #pragma unroll
        for (int j = 0; j < 4; j++) {
            int idx = tid + j * 256;
            int r = idx >> 3;
            int c = (idx & 7) << 2;
            int gr = row0 + r;
            float4 av = make_float4(0.f, 0.f, 0.f, 0.f);
            if (gr < Mr) {
                av = *reinterpret_cast<const float4*>(A + (size_t)gr * K + k0 + c);
                if (LNF) {
                    float2 st = __ldg(stats_in + gr);
                    int fc = k0 + c;
                    av.x = fmaxf((av.x - st.x) * st.y * __ldg(lng + fc + 0) + __ldg(lnb + fc + 0), 0.f);
                    av.y = fmaxf((av.y - st.x) * st.y * __ldg(lng + fc + 1) + __ldg(lnb + fc + 1), 0.f);
                    av.z = fmaxf((av.z - st.x) * st.y * __ldg(lng + fc + 2) + __ldg(lnb + fc + 2), 0.f);
                    av.w = fmaxf((av.w - st.x) * st.y * __ldg(lng + fc + 3) + __ldg(lnb + fc + 3), 0.f);
                }
            }
            float4 h4;
            h4.x = tf32r(av.x); h4.y = tf32r(av.y);
            h4.z = tf32r(av.z); h4.w = tf32r(av.w);
            *reinterpret_cast<float4*>(&As[r][c]) = h4;
            float4 l4;
            l4.x = tf32r(av.x - h4.x); l4.y = tf32r(av.y - h4.y);
            l4.z = tf32r(av.z - h4.z); l4.w = tf32r(av.w - h4.w);
            *reinterpret_cast<float4*>(&AsL[r][c]) = l4;
        }
        #pragma unroll
        for (int j = 0; j < 2; j++) {
            int idx = tid + j * 256;
            int r = idx >> 4;
            int c = (idx & 15) << 2;
            int gc = col0 + c;
            float4 bv = make_float4(0.f, 0.f, 0.f, 0.f);
            if (gc < Nc)
                bv = *reinterpret_cast<const float4*>(B + (size_t)(k0 + r) * Nc + gc);
            float4 h4;
            h4.x = tf32r(bv.x); h4.y = tf32r(bv.y);
            h4.z = tf32r(bv.z); h4.w = tf32r(bv.w);
            *reinterpret_cast<float4*>(&Bs[r][c]) = h4;
            float4 l4;
            l4.x = tf32r(bv.x - h4.x); l4.y = tf32r(bv.y - h4.y);
            l4.z = tf32r(bv.z - h4.z); l4.w = tf32r(bv.w - h4.w);
            *reinterpret_cast<float4*>(&BsL[r][c]) = l4;
        }
        __syncthreads();
        #pragma unroll
        for (int kk = 0; kk < 32; kk += 8) {
            uint32_t ah[2][4], bh[4][2], al[2][4], bl[4][2];
            int ar = wm * 32 + grp;
            #pragma unroll
            for (int mi = 0; mi < 2; mi++) {
                ah[mi][0] = __float_as_uint(As[ar + mi * 16][kk + tg]);
                ah[mi][1] = __float_as_uint(As[ar + mi * 16 + 8][kk + tg]);
                ah[mi][2] = __float_as_uint(As[ar + mi * 16][kk + tg + 4]);
                ah[mi][3] = __float_as_uint(As[ar + mi * 16 + 8][kk + tg + 4]);
                al[mi][0] = __float_as_uint(AsL[ar + mi * 16][kk + tg]);
                al[mi][1] = __float_as_uint(AsL[ar + mi * 16 + 8][kk + tg]);
                al[mi][2] = __float_as_uint(AsL[ar + mi * 16][kk + tg + 4]);
                al[mi][3] = __float_as_uint(AsL[ar + mi * 16 + 8][kk + tg + 4]);
            }
            #pragma unroll
            for (int ni = 0; ni < 4; ni++) {
                int bcn = wn * 32 + ni * 8 + grp;
                bh[ni][0] = __float_as_uint(Bs[kk + tg][bcn]);
                bh[ni][1] = __float_as_uint(Bs[kk + tg + 4][bcn]);
                bl[ni][0] = __float_as_uint(BsL[kk + tg][bcn]);
                bl[ni][1] = __float_as_uint(BsL[kk + tg + 4][bcn]);
            }
            #pragma unroll
            for (int mi = 0; mi < 2; mi++)
                #pragma unroll
                for (int ni = 0; ni < 4; ni++) {
                    mma_tf32(acc[mi][ni], ah[mi], bl[ni]);
                    mma_tf32(acc[mi][ni], al[mi], bh[ni]);
                    mma_tf32(acc[mi][ni], ah[mi], bh[ni]);
                }
        }
        __syncthreads();
    }

    #pragma unroll
    for (int mi = 0; mi < 2; mi++) {
        int r0 = row0 + wm * 32 + mi * 16 + grp;
        #pragma unroll
        for (int ni = 0; ni < 4; ni++) {
            int c = col0 + wn * 32 + ni * 8 + tg * 2;
            if (c >= Nc) continue;
            #pragma unroll
            for (int half = 0; half < 2; half++) {
                int r = r0 + half * 8;
                if (r >= Mr) continue;
                float v0 = acc[mi][ni][half * 2] + (bias ? bias[c] : 0.f);
                float v1 = acc[mi][ni][half * 2 + 1] + (bias ? bias[c + 1] : 0.f);
                C[(size_t)r * Nc + c]     = v0;
                C[(size_t)r * Nc + c + 1] = v1;
            }
        }
    }
}

// ---------------- fused per-node edge aggregation (softmax, all-fp16 gathers) ----------------
__device__ __forceinline__ void edge_accum(
    uint4 kr, uint4 vr, uint4 er, const float* qr, const float* pr,
    float* acc, float* rac, float& den)
{
    const __half2* kh = reinterpret_cast<const __half2*>(&kr);
    const __half2* vh = reinterpret_cast<const __half2*>(&vr);
    const __half2* eh = reinterpret_cast<const __half2*>(&er);
    float2 k0 = __half22float2(kh[0]), k1 = __half22float2(kh[1]);
    float2 k2 = __half22float2(kh[2]), k3 = __half22float2(kh[3]);
    float2 e0 = __half22float2(eh[0]), e1 = __half22float2(eh[1]);
    float2 e2 = __half22float2(eh[2]), e3 = __half22float2(eh[3]);
    float2 v0 = __half22float2(vh[0]), v1 = __half22float2(vh[1]);
    float2 v2 = __half22float2(vh[2]), v3 = __half22float2(vh[3]);

    float s = qr[0]*k0.x + qr[1]*k0.y + qr[2]*k1.x + qr[3]*k1.y
            + qr[4]*k2.x + qr[5]*k2.y + qr[6]*k3.x + qr[7]*k3.y
            + pr[0]*e0.x + pr[1]*e0.y + pr[2]*e1.x + pr[3]*e1.y
            + pr[4]*e2.x + pr[5]*e2.y + pr[6]*e3.x + pr[7]*e3.y;
    s += __shfl_xor_sync(0xffffffffu, s, 1, 8);
    s += __shfl_xor_sync(0xffffffffu, s, 2, 8);
    s += __shfl_xor_sync(0xffffffffu, s, 4, 8);
    float w = __expf(s * 0.125f);

    den += w;
    acc[0] += w*v0.x;  acc[1] += w*v0.y;
    acc[2] += w*v1.x;  acc[3] += w*v1.y;
    acc[4] += w*v2.x;  acc[5] += w*v2.y;
    acc[6] += w*v3.x;  acc[7] += w*v3.y;
    rac[0] += w*e0.x;  rac[1] += w*e0.y;
    rac[2] += w*e1.x;  rac[3] += w*e1.y;
    rac[4] += w*e2.x;  rac[5] += w*e2.y;
    rac[6] += w*e3.x;  rac[7] += w*e3.y;
}

// One warp per node; simple 2-unrolled loop (R15 configuration — fastest measured).
// qkvh: half [node][1024] q@0 k@256 v@512 p@768. eash: half [epos][64].
__global__ __launch_bounds__(256) void edge_agg_kernel(
    const int* __restrict__ off, const int* __restrict__ csrc,
    const __half* __restrict__ eash, const __half* __restrict__ qkvh,
    float* __restrict__ A1, __half* __restrict__ Rh)
{
    int gw = (blockIdx.x * blockDim.x + threadIdx.x) >> 5;
    if (gw >= NN) return;
    int lane = threadIdx.x & 31;
    int ch0 = lane << 3;
    int ealn = (lane & 7) << 3;

    float qr[8], pr[8];
    {
        const __half* qpp = qkvh + (size_t)gw * 1024 + ch0;
        uint4 qu = *reinterpret_cast<const uint4*>(qpp);
        uint4 pu = *reinterpret_cast<const uint4*>(qpp + 768);
        const __half2* qh = reinterpret_cast<const __half2*>(&qu);
        const __half2* ph = reinterpret_cast<const __half2*>(&pu);
        #pragma unroll
        for (int i = 0; i < 4; i++) {
            float2 qf = __half22float2(qh[i]);
            float2 pf = __half22float2(ph[i]);
            qr[2*i] = qf.x; qr[2*i+1] = qf.y;
            pr[2*i] = pf.x; pr[2*i+1] = pf.y;
        }
    }
    float den = 0.f;
    float acc[8], rac[8];
    #pragma unroll
    for (int r = 0; r < 8; r++) { acc[r] = 0.f; rac[r] = 0.f; }

    int beg = off[gw], end = off[gw + 1];
    int epos = beg;
    int n2 = beg + ((end - beg) & ~1);
    for (; epos < n2; epos += 2) {
        int s0 = __ldg(csrc + epos);
        int s1 = __ldg(csrc + epos + 1);
        const __half* kp0 = qkvh + (size_t)s0 * 1024 + 256 + ch0;
        const __half* kp1 = qkvh + (size_t)s1 * 1024 + 256 + ch0;
        uint4 kr0 = *reinterpret_cast<const uint4*>(kp0);
        uint4 vr0 = *reinterpret_cast<const uint4*>(kp0 + 256);
        uint4 er0 = *reinterpret_cast<const uint4*>(eash + (size_t)epos * 64 + ealn);
        uint4 kr1 = *reinterpret_cast<const uint4*>(kp1);
        uint4 vr1 = *reinterpret_cast<const uint4*>(kp1 + 256);
        uint4 er1 = *reinterpret_cast<const uint4*>(eash + (size_t)(epos + 1) * 64 + ealn);
        edge_accum(kr0, vr0, er0, qr, pr, acc, rac, den);
        edge_accum(kr1, vr1, er1, qr, pr, acc, rac, den);
    }
    if (epos < end) {
        int s0 = __ldg(csrc + epos);
        const __half* kp0 = qkvh + (size_t)s0 * 1024 + 256 + ch0;
        uint4 kr0 = *reinterpret_cast<const uint4*>(kp0);
        uint4 vr0 = *reinterpret_cast<const uint4*>(kp0 + 256);
        uint4 er0 = *reinterpret_cast<const uint4*>(eash + (size_t)epos * 64 + ealn);
        edge_accum(kr0, vr0, er0, qr, pr, acc, rac, den);
    }

    float dinv = 1.f / (den + 1e-16f);
    float a1[8];
    #pragma unroll
    for (int r = 0; r < 8; r++) a1[r] = acc[r] * dinv * 0.25f;
    #pragma unroll
    for (int r = 0; r < 8; r++) {
        a1[r] += __shfl_xor_sync(0xffffffffu, a1[r], 8);
        a1[r] += __shfl_xor_sync(0xffffffffu, a1[r], 16);
    }
    if (lane < 8) {
        *reinterpret_cast<float4*>(A1 + (size_t)gw * 64 + ealn) =
            make_float4(a1[0], a1[1], a1[2], a1[3]);
        *reinterpret_cast<float4*>(A1 + (size_t)gw * 64 + ealn + 4) =
            make_float4(a1[4], a1[5], a1[6], a1[7]);
    }
    uint4 ru;
    __half2 r0 = __floats2half2_rn(rac[0] * dinv, rac[1] * dinv);
    __half2 r1 = __floats2half2_rn(rac[2] * dinv, rac[3] * dinv);
    __half2 r2 = __floats2half2_rn(rac[4] * dinv, rac[5] * dinv);
    __half2 r3 = __floats2half2_rn(rac[6] * dinv, rac[7] * dinv);
    ru.x = *reinterpret_cast<uint32_t*>(&r0);
    ru.y = *reinterpret_cast<uint32_t*>(&r1);
    ru.z = *reinterpret_cast<uint32_t*>(&r2);
    ru.w = *reinterpret_cast<uint32_t*>(&r3);
    *reinterpret_cast<uint4*>(Rh + (size_t)gw * 256 + ch0) = ru;
}

// ---------------- host launch ----------------
extern "C" void kernel_launch(void* const* d_in, const int* in_sizes, int n_in,
                              void* d_out, int out_size) {
    const float* x         = (const float*)d_in[0];
    const int*   ei        = (const int*)  d_in[1];
    const float* edge_attr = (const float*)d_in[2];
    const float* node_W    = (const float*)d_in[3];
    const float* node_b    = (const float*)d_in[4];
    const float* eenc_W    = (const float*)d_in[5];
    const float* eenc_b    = (const float*)d_in[6];
    const float* Wq        = (const float*)d_in[7];
    const float* bq        = (const float*)d_in[8];
    const float* Wk        = (const float*)d_in[9];
    const float* bk        = (const float*)d_in[10];
    const float* Wv        = (const float*)d_in[11];
    const float* bv        = (const float*)d_in[12];
    const float* We        = (const float*)d_in[13];
    const float* Wskip     = (const float*)d_in[14];
    const float* bskip     = (const float*)d_in[15];
    const float* ln_g      = (const float*)d_in[16];
    const float* ln_b      = (const float*)d_in[17];
    const float* lin_W     = (const float*)d_in[18];
    const float* lin_b     = (const float*)d_in[19];
    float* out = (float*)d_out;

    cudaFuncSetAttribute(gemm_tf32x3_kernel<false>,
                         cudaFuncAttributeMaxDynamicSharedMemorySize, SMEM_TRIPLE_BYTES);
    cudaFuncSetAttribute(gemm_tf32x3_kernel<true>,
                         cudaFuncAttributeMaxDynamicSharedMemorySize, SMEM_TRIPLE_BYTES);

    float *h_, *A1_, *skip_, *Wc_, *bc_, *M_;
    float2* stats_;
    __half *qkvh_, *eash_, *Rh_;
    int *deg_, *off_, *cur_, *csrc_, *ceid_;
    cudaGetSymbolAddress((void**)&h_,    g_h);
    cudaGetSymbolAddress((void**)&A1_,   g_A1);
    cudaGetSymbolAddress((void**)&skip_, g_skip);
    cudaGetSymbolAddress((void**)&qkvh_, g_qkvh);
    cudaGetSymbolAddress((void**)&Rh_,   g_Rh);
    cudaGetSymbolAddress((void**)&eash_, g_eash);
    cudaGetSymbolAddress((void**)&stats_,g_stats);
    cudaGetSymbolAddress((void**)&Wc_,   g_Wc);
    cudaGetSymbolAddress((void**)&bc_,   g_bc);
    cudaGetSymbolAddress((void**)&M_,    g_M);
    cudaGetSymbolAddress((void**)&deg_,  g_deg);
    cudaGetSymbolAddress((void**)&off_,  g_off);
    cudaGetSymbolAddress((void**)&cur_,  g_cur);
    cudaGetSymbolAddress((void**)&csrc_, g_csrc);
    cudaGetSymbolAddress((void**)&ceid_, g_ceid);

    // Fork a side stream inside capture: side chain runs node encoder + weight
    // prep concurrently with the CSR build + edge encoder on the main stream.
    // Streams/events are created per call and intentionally not destroyed
    // (destroying a capturing stream is an error; only ~3 real calls happen).
    cudaStream_t s1;
    cudaEvent_t evFork, evJoin;
    cudaStreamCreateWithFlags(&s1, cudaStreamNonBlocking);
    cudaEventCreateWithFlags(&evFork, cudaEventDisableTiming);
    cudaEventCreateWithFlags(&evJoin, cudaEventDisableTiming);
    cudaEventRecord(evFork, 0);
    cudaStreamWaitEvent(s1, evFork, 0);

    // ---- side stream: weight prep + node encoder (independent of CSR) ----
    prep_comb_kernel<<<(LL * 65 * NCOMB + 255) / 256, 256, 0, s1>>>(
        Wq, bq, Wk, bk, Wv, bv, We, Wskip, bskip, Wc_, bc_);
    prep_m_kernel<<<(LL * HC * HID + 255) / 256, 256, 0, s1>>>(We, M_);
    {
        dim3 grid(1, (NN + 127) / 128);
        gemm_tf32x3_kernel<false><<<grid, 256, SMEM_TRIPLE_BYTES, s1>>>(
            x, node_W, node_b, nullptr, nullptr, nullptr, h_, NN, 128, 64);
    }
    cudaEventRecord(evJoin, s1);

    // ---- main stream: CSR build + edge encoder ----
    zero_int_kernel<<<(NN + 255) / 256, 256>>>(deg_, NN);
    hist_kernel<<<(EE + 255) / 256, 256>>>(ei, deg_, EE);
    scan_kernel<<<1, 1024>>>(deg_, off_, cur_, NN, EE);
    scatter_kernel<<<(EE + 255) / 256, 256>>>(ei, cur_, csrc_, ceid_, EE);
    {
        dim3 grid(1, (EE + 127) / 128);
        gemm_f16_kernel<false, false, false><<<grid, 256>>>(
            edge_attr, nullptr, ceid_, eenc_W, eenc_b, nullptr, nullptr, nullptr,
            nullptr, nullptr, nullptr, nullptr, eash_, nullptr, nullptr, EE, 64, 64);
    }

    // join side chain before the layer loop
    cudaStreamWaitEvent(0, evJoin, 0);

    const int rowsN = (NN + 127) / 128;
    for (int l = 0; l < LL; l++) {
        // fused [q|k|v|p|skip] GEMM; layers>0 fuse LN+ReLU via stats from prev R@M
        dim3 grid((NCOMB + 63) / 64, rowsN);
        if (l == 0) {
            gemm_f16_kernel<false, false, false><<<grid, 256>>>(
                h_, nullptr, nullptr, Wc_ + l * HID * NCOMB, bc_ + l * NCOMB,
                nullptr, nullptr, nullptr,
                nullptr, nullptr, nullptr, skip_, nullptr, qkvh_, nullptr, NN, 64, NCOMB);
        } else {
            gemm_f16_kernel<true, false, false><<<grid, 256>>>(
                h_, nullptr, nullptr, Wc_ + l * HID * NCOMB, bc_ + l * NCOMB,
                stats_, ln_g + l * 64, ln_b + l * 64,
                nullptr, nullptr, nullptr, skip_, nullptr, qkvh_, nullptr, NN, 64, NCOMB);
        }
        edge_agg_kernel<<<(NN * 32) / 256, 256>>>(off_, csrc_, eash_, qkvh_, A1_, Rh_);
        // h = Rh@M + A1 + skip (+ h residual for l>0); emit per-row LN stats; A in fp16
        dim3 grid2(1, rowsN);
        gemm_f16_kernel<false, true, true><<<grid2, 256>>>(
            nullptr, Rh_, nullptr, M_ + l * HC * HID, nullptr,
            nullptr, nullptr, nullptr,
            A1_, skip_, (l > 0 ? h_ : nullptr), h_, nullptr, nullptr, stats_, NN, 256, 64);
    }

    // head: LN(g[0],b[0])+ReLU fused into A-load, 3xTF32
    {
        dim3 grid(1, rowsN);
        gemm_tf32x3_kernel<true><<<grid, 256, SMEM_TRIPLE_BYTES>>>(
            h_, lin_W, lin_b, stats_, ln_g, ln_b, out, NN, 64, 32);
    }
}